// round 3
// baseline (speedup 1.0000x reference)
#include <cuda_runtime.h>
#include <cfloat>
#include <climits>

// Problem geometry (fixed by the dataset instance):
//   data_in : [1, 512] f32    (d_in[0])
//   ukb_mat : [200000, 512] f32 (d_in[1])
//   pseudo  : [200000] f32    (d_in[2])
//   K       : 3               (d_in[3], compile-time constant here)
// out: [1] f32 = mean(pseudo[argmin-3 of L1 distances])

constexpr int D        = 512;
constexpr int KSEL     = 3;
constexpr int BLOCKS1  = 1184;            // 8 blocks/SM * 148 SMs
constexpr int THREADS1 = 256;             // 8 warps
constexpr int WARPS1   = THREADS1 / 32;
constexpr int NCAND    = BLOCKS1 * KSEL;  // 3552 candidates
constexpr int THREADS2 = 128;

// Scratch (no device allocation allowed) — candidate (dist, idx) per block.
__device__ float g_cand_dist[NCAND];
__device__ int   g_cand_idx [NCAND];

// Maintain dd[0]<=dd[1]<=dd[2]; tie broken toward smaller index (matches
// jax.lax.top_k stable ordering on the negated distances).
__device__ __forceinline__ void top3_insert(float d, int idx, float dd[3], int ii[3]) {
    if (d < dd[2] || (d == dd[2] && idx < ii[2])) {
        dd[2] = d; ii[2] = idx;
        if (dd[2] < dd[1] || (dd[2] == dd[1] && ii[2] < ii[1])) {
            float td = dd[1]; int ti = ii[1];
            dd[1] = dd[2]; ii[1] = ii[2]; dd[2] = td; ii[2] = ti;
            if (dd[1] < dd[0] || (dd[1] == dd[0] && ii[1] < ii[0])) {
                td = dd[0]; ti = ii[0];
                dd[0] = dd[1]; ii[0] = ii[1]; dd[1] = td; ii[1] = ti;
            }
        }
    }
}

__device__ __forceinline__ float l1_4(float4 a, float4 q) {
    return fabsf(a.x - q.x) + fabsf(a.y - q.y) + fabsf(a.z - q.z) + fabsf(a.w - q.w);
}

__global__ __launch_bounds__(THREADS1)
void dist_topk_kernel(const float* __restrict__ query,
                      const float* __restrict__ mat,
                      int N) {
    __shared__ float sq[D];
    for (int i = threadIdx.x; i < D; i += THREADS1) sq[i] = query[i];
    __syncthreads();

    const int lane  = threadIdx.x & 31;
    const int warp  = threadIdx.x >> 5;
    const int gwarp = blockIdx.x * WARPS1 + warp;
    const int nwarp = BLOCKS1 * WARPS1;

    // Query slice for this lane, in registers for the whole sweep.
    const float4* sq4 = reinterpret_cast<const float4*>(sq);
    const float4 q0 = sq4[lane +  0];
    const float4 q1 = sq4[lane + 32];
    const float4 q2 = sq4[lane + 64];
    const float4 q3 = sq4[lane + 96];

    float dd[3] = {FLT_MAX, FLT_MAX, FLT_MAX};
    int   ii[3] = {INT_MAX, INT_MAX, INT_MAX};

    for (int row = gwarp; row < N; row += nwarp) {
        const float4* r = reinterpret_cast<const float4*>(mat + (size_t)row * D);
        // 4 independent 128-bit loads per lane -> MLP_p1=4, fully coalesced 2KB/row.
        float4 a0 = r[lane +  0];
        float4 a1 = r[lane + 32];
        float4 a2 = r[lane + 64];
        float4 a3 = r[lane + 96];
        float s = l1_4(a0, q0) + l1_4(a1, q1) + l1_4(a2, q2) + l1_4(a3, q3);
        #pragma unroll
        for (int o = 16; o > 0; o >>= 1)
            s += __shfl_xor_sync(0xFFFFFFFFu, s, o);
        if (lane == 0) top3_insert(s, row, dd, ii);
    }

    // Block-level merge of the 8 warps' top-3.
    __shared__ float sd[WARPS1 * KSEL];
    __shared__ int   si[WARPS1 * KSEL];
    if (lane == 0) {
        #pragma unroll
        for (int k = 0; k < KSEL; k++) {
            sd[warp * KSEL + k] = dd[k];
            si[warp * KSEL + k] = ii[k];
        }
    }
    __syncthreads();
    if (threadIdx.x == 0) {
        float bd[3] = {FLT_MAX, FLT_MAX, FLT_MAX};
        int   bi[3] = {INT_MAX, INT_MAX, INT_MAX};
        #pragma unroll
        for (int j = 0; j < WARPS1 * KSEL; j++) top3_insert(sd[j], si[j], bd, bi);
        #pragma unroll
        for (int k = 0; k < KSEL; k++) {
            g_cand_dist[blockIdx.x * KSEL + k] = bd[k];
            g_cand_idx [blockIdx.x * KSEL + k] = bi[k];
        }
    }
}

__global__ __launch_bounds__(THREADS2)
void final_reduce_kernel(const float* __restrict__ pseudo,
                         float* __restrict__ out) {
    float dd[3] = {FLT_MAX, FLT_MAX, FLT_MAX};
    int   ii[3] = {INT_MAX, INT_MAX, INT_MAX};
    for (int j = threadIdx.x; j < NCAND; j += THREADS2)
        top3_insert(g_cand_dist[j], g_cand_idx[j], dd, ii);

    __shared__ float sd[THREADS2 * KSEL];
    __shared__ int   si[THREADS2 * KSEL];
    #pragma unroll
    for (int k = 0; k < KSEL; k++) {
        sd[threadIdx.x * KSEL + k] = dd[k];
        si[threadIdx.x * KSEL + k] = ii[k];
    }
    __syncthreads();
    if (threadIdx.x == 0) {
        float bd[3] = {FLT_MAX, FLT_MAX, FLT_MAX};
        int   bi[3] = {INT_MAX, INT_MAX, INT_MAX};
        for (int j = 0; j < THREADS2 * KSEL; j++) top3_insert(sd[j], si[j], bd, bi);
        out[0] = (pseudo[bi[0]] + pseudo[bi[1]] + pseudo[bi[2]]) * (1.0f / 3.0f);
    }
}

extern "C" void kernel_launch(void* const* d_in, const int* in_sizes, int n_in,
                              void* d_out, int out_size) {
    const float* query  = (const float*)d_in[0];
    const float* mat    = (const float*)d_in[1];
    const float* pseudo = (const float*)d_in[2];
    float* out = (float*)d_out;
    const int N = in_sizes[2];   // rows = pseudo element count

    dist_topk_kernel<<<BLOCKS1, THREADS1>>>(query, mat, N);
    final_reduce_kernel<<<1, THREADS2>>>(pseudo, out);
}

// round 4
// speedup vs baseline: 1.2379x; 1.2379x over previous
#include <cuda_runtime.h>
#include <cfloat>
#include <climits>

// Problem geometry:
//   data_in : [1, 512] f32      (d_in[0])
//   ukb_mat : [200000, 512] f32 (d_in[1])
//   pseudo  : [200000] f32      (d_in[2])
//   K       : 3
// out: [1] f32 = mean(pseudo[indices of 3 smallest L1 distances])
//
// Single fused kernel: grid-stride L1-distance stream with per-warp top-3,
// block merge, then last-block-done global merge (packed u64 keys).

constexpr int D        = 512;
constexpr int KSEL     = 3;
constexpr int BLOCKS1  = 1184;            // streaming grid
constexpr int THREADS1 = 256;             // 8 warps
constexpr int WARPS1   = THREADS1 / 32;
constexpr int NCAND    = BLOCKS1 * KSEL;  // 3552 candidate keys

// Scratch (no device allocation allowed).
__device__ unsigned long long g_cand[NCAND];
__device__ unsigned int       g_counter;   // zero-initialized; last block resets it

// key = (float_bits(dist) << 32) | idx.  dist >= 0 so float-bit order == numeric
// order; ties on dist resolve to the smaller index — matches jax.lax.top_k.
__device__ __forceinline__ unsigned long long mkkey(float d, unsigned idx) {
    return ((unsigned long long)__float_as_uint(d) << 32) | idx;
}

constexpr unsigned long long KEY_MAX = 0xFFFFFFFFFFFFFFFFull;

// Keep k[0] <= k[1] <= k[2].
__device__ __forceinline__ void insert3(unsigned long long v, unsigned long long k[3]) {
    if (v < k[2]) {
        k[2] = v;
        if (k[2] < k[1]) { unsigned long long t = k[1]; k[1] = k[2]; k[2] = t;
            if (k[1] < k[0]) { t = k[0]; k[0] = k[1]; k[1] = t; }
        }
    }
}

// Warp-wide merge: after this, every lane holds the warp's global top-3.
__device__ __forceinline__ void warp_merge3(unsigned long long k[3]) {
    #pragma unroll
    for (int o = 16; o > 0; o >>= 1) {
        unsigned long long b0 = __shfl_xor_sync(0xFFFFFFFFu, k[0], o);
        unsigned long long b1 = __shfl_xor_sync(0xFFFFFFFFu, k[1], o);
        unsigned long long b2 = __shfl_xor_sync(0xFFFFFFFFu, k[2], o);
        insert3(b0, k); insert3(b1, k); insert3(b2, k);
    }
}

__device__ __forceinline__ float l1_4(float4 a, float4 q) {
    return fabsf(a.x - q.x) + fabsf(a.y - q.y) + fabsf(a.z - q.z) + fabsf(a.w - q.w);
}

__global__ __launch_bounds__(THREADS1)
void knn_fused_kernel(const float* __restrict__ query,
                      const float* __restrict__ mat,
                      const float* __restrict__ pseudo,
                      float* __restrict__ out,
                      int N) {
    __shared__ float sq[D];
    for (int i = threadIdx.x; i < D; i += THREADS1) sq[i] = query[i];
    __syncthreads();

    const int lane  = threadIdx.x & 31;
    const int warp  = threadIdx.x >> 5;
    const int gwarp = blockIdx.x * WARPS1 + warp;
    const int nwarp = BLOCKS1 * WARPS1;

    // Query slice in registers for the whole sweep.
    const float4* sq4 = reinterpret_cast<const float4*>(sq);
    const float4 q0 = sq4[lane +  0];
    const float4 q1 = sq4[lane + 32];
    const float4 q2 = sq4[lane + 64];
    const float4 q3 = sq4[lane + 96];

    unsigned long long k[3] = {KEY_MAX, KEY_MAX, KEY_MAX};

    for (int row = gwarp; row < N; row += nwarp) {
        const float4* r = reinterpret_cast<const float4*>(mat + (size_t)row * D);
        // 4 independent 128-bit loads per lane, fully coalesced 2KB/row.
        float4 a0 = r[lane +  0];
        float4 a1 = r[lane + 32];
        float4 a2 = r[lane + 64];
        float4 a3 = r[lane + 96];
        float s = l1_4(a0, q0) + l1_4(a1, q1) + l1_4(a2, q2) + l1_4(a3, q3);
        #pragma unroll
        for (int o = 16; o > 0; o >>= 1)
            s += __shfl_xor_sync(0xFFFFFFFFu, s, o);
        if (lane == 0) insert3(mkkey(s, (unsigned)row), k);
    }

    // Block merge: lane 0 of each warp has the warp's top-3.
    __shared__ unsigned long long sk[WARPS1 * KSEL];
    if (lane == 0) {
        #pragma unroll
        for (int j = 0; j < KSEL; j++) sk[warp * KSEL + j] = k[j];
    }
    __syncthreads();
    if (threadIdx.x == 0) {
        unsigned long long bk[3] = {KEY_MAX, KEY_MAX, KEY_MAX};
        #pragma unroll
        for (int j = 0; j < WARPS1 * KSEL; j++) insert3(sk[j], bk);
        #pragma unroll
        for (int j = 0; j < KSEL; j++) g_cand[blockIdx.x * KSEL + j] = bk[j];
    }

    // Last-block-done: the final arriving block merges all candidates.
    __shared__ int s_last;
    if (threadIdx.x == 0) {
        __threadfence();
        unsigned v = atomicAdd(&g_counter, 1u);
        s_last = (v == BLOCKS1 - 1) ? 1 : 0;
    }
    __syncthreads();
    if (!s_last) return;

    // All 256 threads of the last block scan the 3552 candidates in parallel.
    unsigned long long m[3] = {KEY_MAX, KEY_MAX, KEY_MAX};
    volatile unsigned long long* cand = g_cand;   // bypass stale L1
    for (int j = threadIdx.x; j < NCAND; j += THREADS1)
        insert3(cand[j], m);
    warp_merge3(m);

    __shared__ unsigned long long fk[WARPS1 * KSEL];
    if (lane == 0) {
        #pragma unroll
        for (int j = 0; j < KSEL; j++) fk[warp * KSEL + j] = m[j];
    }
    __syncthreads();
    if (threadIdx.x == 0) {
        unsigned long long bk[3] = {KEY_MAX, KEY_MAX, KEY_MAX};
        #pragma unroll
        for (int j = 0; j < WARPS1 * KSEL; j++) insert3(fk[j], bk);
        unsigned i0 = (unsigned)(bk[0] & 0xFFFFFFFFull);
        unsigned i1 = (unsigned)(bk[1] & 0xFFFFFFFFull);
        unsigned i2 = (unsigned)(bk[2] & 0xFFFFFFFFull);
        out[0] = (pseudo[i0] + pseudo[i1] + pseudo[i2]) * (1.0f / 3.0f);
        g_counter = 0;   // self-reset for the next graph replay
    }
}

extern "C" void kernel_launch(void* const* d_in, const int* in_sizes, int n_in,
                              void* d_out, int out_size) {
    const float* query  = (const float*)d_in[0];
    const float* mat    = (const float*)d_in[1];
    const float* pseudo = (const float*)d_in[2];
    float* out = (float*)d_out;
    const int N = in_sizes[2];   // rows = pseudo element count

    knn_fused_kernel<<<BLOCKS1, THREADS1>>>(query, mat, pseudo, out, N);
}

// round 7
// speedup vs baseline: 1.3570x; 1.0962x over previous
#include <cuda_runtime.h>
#include <cfloat>
#include <climits>

// Problem geometry:
//   data_in : [1, 512] f32      (d_in[0])
//   ukb_mat : [200000, 512] f32 (d_in[1])
//   pseudo  : [200000] f32      (d_in[2])
//   K       : 3
// out: [1] f32 = mean(pseudo[indices of 3 smallest L1 distances])
//
// Fused single kernel. Each warp processes TWO rows per iteration:
// 8 independent LDG.128 (4KB in flight), then a packed dual warp reduction
// (6 shuffles for both rows). Lane 0 tracks row a's top-3, lane 16 row b's;
// a final warp merge reconciles. Last-block-done merges all block candidates.

constexpr int D        = 512;
constexpr int KSEL     = 3;
constexpr int BLOCKS1  = 1184;            // 8 per SM quantum on 148 SMs
constexpr int THREADS1 = 256;             // 8 warps
constexpr int WARPS1   = THREADS1 / 32;
constexpr int NCAND    = BLOCKS1 * KSEL;  // 3552 candidate keys

__device__ unsigned long long g_cand[NCAND];
__device__ unsigned int       g_counter;   // zero-init; self-reset each run

// key = (float_bits(dist) << 32) | idx. dist >= 0 so float-bit order ==
// numeric order; ties resolve to smaller index — matches jax.lax.top_k.
__device__ __forceinline__ unsigned long long mkkey(float d, unsigned idx) {
    return ((unsigned long long)__float_as_uint(d) << 32) | idx;
}

constexpr unsigned long long KEY_MAX = 0xFFFFFFFFFFFFFFFFull;

__device__ __forceinline__ void insert3(unsigned long long v, unsigned long long k[3]) {
    if (v < k[2]) {
        k[2] = v;
        if (k[2] < k[1]) { unsigned long long t = k[1]; k[1] = k[2]; k[2] = t;
            if (k[1] < k[0]) { t = k[0]; k[0] = k[1]; k[1] = t; }
        }
    }
}

__device__ __forceinline__ void warp_merge3(unsigned long long k[3]) {
    #pragma unroll
    for (int o = 16; o > 0; o >>= 1) {
        unsigned long long b0 = __shfl_xor_sync(0xFFFFFFFFu, k[0], o);
        unsigned long long b1 = __shfl_xor_sync(0xFFFFFFFFu, k[1], o);
        unsigned long long b2 = __shfl_xor_sync(0xFFFFFFFFu, k[2], o);
        insert3(b0, k); insert3(b1, k); insert3(b2, k);
    }
}

__device__ __forceinline__ float l1_4(float4 a, float4 q) {
    return fabsf(a.x - q.x) + fabsf(a.y - q.y) + fabsf(a.z - q.z) + fabsf(a.w - q.w);
}

__global__ __launch_bounds__(THREADS1, 3)
void knn_fused_kernel(const float* __restrict__ query,
                      const float* __restrict__ mat,
                      const float* __restrict__ pseudo,
                      float* __restrict__ out,
                      int N) {
    __shared__ float sq[D];
    for (int i = threadIdx.x; i < D; i += THREADS1) sq[i] = query[i];
    __syncthreads();

    const int lane  = threadIdx.x & 31;
    const int warp  = threadIdx.x >> 5;
    const int gwarp = blockIdx.x * WARPS1 + warp;
    const int nwarp = BLOCKS1 * WARPS1;

    const float4* sq4 = reinterpret_cast<const float4*>(sq);
    const float4 q0 = sq4[lane +  0];
    const float4 q1 = sq4[lane + 32];
    const float4 q2 = sq4[lane + 64];
    const float4 q3 = sq4[lane + 96];

    unsigned long long k[3] = {KEY_MAX, KEY_MAX, KEY_MAX};

    int row = 2 * gwarp;
    const int stride = 2 * nwarp;
    for (; row + 1 < N; row += stride) {
        const float4* ra = reinterpret_cast<const float4*>(mat + (size_t)row * D);
        const float4* rb = reinterpret_cast<const float4*>(mat + (size_t)(row + 1) * D);
        // 8 independent streaming 128-bit loads -> 4KB in flight per warp.
        float4 a0 = __ldcs(ra + lane +  0);
        float4 a1 = __ldcs(ra + lane + 32);
        float4 a2 = __ldcs(ra + lane + 64);
        float4 a3 = __ldcs(ra + lane + 96);
        float4 b0 = __ldcs(rb + lane +  0);
        float4 b1 = __ldcs(rb + lane + 32);
        float4 b2 = __ldcs(rb + lane + 64);
        float4 b3 = __ldcs(rb + lane + 96);

        float sa = l1_4(a0, q0) + l1_4(a1, q1) + l1_4(a2, q2) + l1_4(a3, q3);
        float sb = l1_4(b0, q0) + l1_4(b1, q1) + l1_4(b2, q2) + l1_4(b3, q3);

        // Packed dual reduction: one xor-16 step folds each row to 16 partials,
        // lower half carries row a, upper half row b; 4-step butterfly finishes both.
        float va = sa + __shfl_xor_sync(0xFFFFFFFFu, sa, 16);
        float vb = sb + __shfl_xor_sync(0xFFFFFFFFu, sb, 16);
        float v  = (lane < 16) ? va : vb;
        #pragma unroll
        for (int o = 8; o > 0; o >>= 1)
            v += __shfl_xor_sync(0xFFFFFFFFu, v, o);
        // lane 0 holds row a's sum, lane 16 holds row b's sum.
        if (lane == 0)       insert3(mkkey(v, (unsigned)row),     k);
        else if (lane == 16) insert3(mkkey(v, (unsigned)(row+1)), k);
    }
    // Tail (N odd): at most one leftover row.
    if (row < N) {
        const float4* ra = reinterpret_cast<const float4*>(mat + (size_t)row * D);
        float4 a0 = __ldcs(ra + lane +  0);
        float4 a1 = __ldcs(ra + lane + 32);
        float4 a2 = __ldcs(ra + lane + 64);
        float4 a3 = __ldcs(ra + lane + 96);
        float s = l1_4(a0, q0) + l1_4(a1, q1) + l1_4(a2, q2) + l1_4(a3, q3);
        #pragma unroll
        for (int o = 16; o > 0; o >>= 1)
            s += __shfl_xor_sync(0xFFFFFFFFu, s, o);
        if (lane == 0) insert3(mkkey(s, (unsigned)row), k);
    }

    // Merge lanes 0 and 16 (others hold KEY_MAX), then block merge.
    warp_merge3(k);

    __shared__ unsigned long long sk[WARPS1 * KSEL];
    if (lane == 0) {
        #pragma unroll
        for (int j = 0; j < KSEL; j++) sk[warp * KSEL + j] = k[j];
    }
    __syncthreads();
    if (threadIdx.x == 0) {
        unsigned long long bk[3] = {KEY_MAX, KEY_MAX, KEY_MAX};
        #pragma unroll
        for (int j = 0; j < WARPS1 * KSEL; j++) insert3(sk[j], bk);
        #pragma unroll
        for (int j = 0; j < KSEL; j++) g_cand[blockIdx.x * KSEL + j] = bk[j];
    }

    // Last-block-done global merge.
    __shared__ int s_last;
    if (threadIdx.x == 0) {
        __threadfence();
        unsigned v = atomicAdd(&g_counter, 1u);
        s_last = (v == BLOCKS1 - 1) ? 1 : 0;
    }
    __syncthreads();
    if (!s_last) return;

    unsigned long long m[3] = {KEY_MAX, KEY_MAX, KEY_MAX};
    volatile unsigned long long* cand = g_cand;
    for (int j = threadIdx.x; j < NCAND; j += THREADS1)
        insert3(cand[j], m);
    warp_merge3(m);

    __shared__ unsigned long long fk[WARPS1 * KSEL];
    if (lane == 0) {
        #pragma unroll
        for (int j = 0; j < KSEL; j++) fk[warp * KSEL + j] = m[j];
    }
    __syncthreads();
    if (threadIdx.x == 0) {
        unsigned long long bk[3] = {KEY_MAX, KEY_MAX, KEY_MAX};
        #pragma unroll
        for (int j = 0; j < WARPS1 * KSEL; j++) insert3(fk[j], bk);
        unsigned i0 = (unsigned)(bk[0] & 0xFFFFFFFFull);
        unsigned i1 = (unsigned)(bk[1] & 0xFFFFFFFFull);
        unsigned i2 = (unsigned)(bk[2] & 0xFFFFFFFFull);
        out[0] = (pseudo[i0] + pseudo[i1] + pseudo[i2]) * (1.0f / 3.0f);
        g_counter = 0;   // reset for next graph replay
    }
}

extern "C" void kernel_launch(void* const* d_in, const int* in_sizes, int n_in,
                              void* d_out, int out_size) {
    const float* query  = (const float*)d_in[0];
    const float* mat    = (const float*)d_in[1];
    const float* pseudo = (const float*)d_in[2];
    float* out = (float*)d_out;
    const int N = in_sizes[2];

    knn_fused_kernel<<<BLOCKS1, THREADS1>>>(query, mat, pseudo, out, N);
}

// round 8
// speedup vs baseline: 1.5063x; 1.1101x over previous
#include <cuda_runtime.h>
#include <cfloat>
#include <climits>

// Problem geometry:
//   data_in : [1, 512] f32      (d_in[0])
//   ukb_mat : [200000, 512] f32 (d_in[1])
//   pseudo  : [200000] f32      (d_in[2])
//   K       : 3
// out: [1] f32 = mean(pseudo[indices of 3 smallest L1 distances])
//
// Fused persistent kernel, software-pipelined: each warp streams row PAIRS
// (8x LDG.128 per pair); the next pair's loads are issued before the current
// pair's reduction, so every warp keeps 4KB in flight during compute.
// Packed dual warp reduction (6 shuffles / 2 rows); packed u64 (dist,idx)
// top-3 keys; last-block-done global merge.

constexpr int D        = 512;
constexpr int KSEL     = 3;
constexpr int BLOCKS1  = 296;             // 2 CTAs/SM * 148 SMs, persistent
constexpr int THREADS1 = 256;             // 8 warps
constexpr int WARPS1   = THREADS1 / 32;
constexpr int NCAND    = BLOCKS1 * KSEL;  // 888 candidate keys

__device__ unsigned long long g_cand[NCAND];
__device__ unsigned int       g_counter;   // zero-init; self-reset each run

// key = (float_bits(dist) << 32) | idx. dist >= 0 so float-bit order ==
// numeric order; ties resolve to smaller index — matches jax.lax.top_k.
__device__ __forceinline__ unsigned long long mkkey(float d, unsigned idx) {
    return ((unsigned long long)__float_as_uint(d) << 32) | idx;
}

constexpr unsigned long long KEY_MAX = 0xFFFFFFFFFFFFFFFFull;

__device__ __forceinline__ void insert3(unsigned long long v, unsigned long long k[3]) {
    if (v < k[2]) {
        k[2] = v;
        if (k[2] < k[1]) { unsigned long long t = k[1]; k[1] = k[2]; k[2] = t;
            if (k[1] < k[0]) { t = k[0]; k[0] = k[1]; k[1] = t; }
        }
    }
}

__device__ __forceinline__ void warp_merge3(unsigned long long k[3]) {
    #pragma unroll
    for (int o = 16; o > 0; o >>= 1) {
        unsigned long long b0 = __shfl_xor_sync(0xFFFFFFFFu, k[0], o);
        unsigned long long b1 = __shfl_xor_sync(0xFFFFFFFFu, k[1], o);
        unsigned long long b2 = __shfl_xor_sync(0xFFFFFFFFu, k[2], o);
        insert3(b0, k); insert3(b1, k); insert3(b2, k);
    }
}

__device__ __forceinline__ float l1_4(float4 a, float4 q) {
    return fabsf(a.x - q.x) + fabsf(a.y - q.y) + fabsf(a.z - q.z) + fabsf(a.w - q.w);
}

struct Pair8 { float4 v[8]; };   // one row pair: v[0..3]=row a, v[4..7]=row b

__device__ __forceinline__ void load_pair(Pair8& p, const float* mat, int row, int lane) {
    const float4* ra = reinterpret_cast<const float4*>(mat + (size_t)row * D);
    const float4* rb = reinterpret_cast<const float4*>(mat + (size_t)(row + 1) * D);
    p.v[0] = __ldcs(ra + lane +  0);
    p.v[1] = __ldcs(ra + lane + 32);
    p.v[2] = __ldcs(ra + lane + 64);
    p.v[3] = __ldcs(ra + lane + 96);
    p.v[4] = __ldcs(rb + lane +  0);
    p.v[5] = __ldcs(rb + lane + 32);
    p.v[6] = __ldcs(rb + lane + 64);
    p.v[7] = __ldcs(rb + lane + 96);
}

__device__ __forceinline__ void reduce_pair(const Pair8& p,
                                            float4 q0, float4 q1, float4 q2, float4 q3,
                                            int row, int lane,
                                            unsigned long long k[3]) {
    float sa = l1_4(p.v[0], q0) + l1_4(p.v[1], q1) + l1_4(p.v[2], q2) + l1_4(p.v[3], q3);
    float sb = l1_4(p.v[4], q0) + l1_4(p.v[5], q1) + l1_4(p.v[6], q2) + l1_4(p.v[7], q3);
    // Packed dual reduction: fold each row to 16 partials, pack a into the
    // lower half-warp and b into the upper, finish with a 4-step butterfly.
    float va = sa + __shfl_xor_sync(0xFFFFFFFFu, sa, 16);
    float vb = sb + __shfl_xor_sync(0xFFFFFFFFu, sb, 16);
    float v  = (lane < 16) ? va : vb;
    #pragma unroll
    for (int o = 8; o > 0; o >>= 1)
        v += __shfl_xor_sync(0xFFFFFFFFu, v, o);
    if (lane == 0)       insert3(mkkey(v, (unsigned)row),       k);
    else if (lane == 16) insert3(mkkey(v, (unsigned)(row + 1)), k);
}

__global__ __launch_bounds__(THREADS1, 2)
void knn_fused_kernel(const float* __restrict__ query,
                      const float* __restrict__ mat,
                      const float* __restrict__ pseudo,
                      float* __restrict__ out,
                      int N) {
    __shared__ float sq[D];
    for (int i = threadIdx.x; i < D; i += THREADS1) sq[i] = query[i];
    __syncthreads();

    const int lane  = threadIdx.x & 31;
    const int warp  = threadIdx.x >> 5;
    const int gwarp = blockIdx.x * WARPS1 + warp;
    const int nwarp = BLOCKS1 * WARPS1;

    const float4* sq4 = reinterpret_cast<const float4*>(sq);
    const float4 q0 = sq4[lane +  0];
    const float4 q1 = sq4[lane + 32];
    const float4 q2 = sq4[lane + 64];
    const float4 q3 = sq4[lane + 96];

    unsigned long long k[3] = {KEY_MAX, KEY_MAX, KEY_MAX};

    const int stride = 2 * nwarp;
    int row = 2 * gwarp;

    Pair8 cur, nxt;
    if (row + 1 < N) {
        load_pair(cur, mat, row, lane);
        // Pipelined main loop: issue next pair's loads, then reduce current.
        for (; row + 1 < N; row += stride) {
            int nrow = row + stride;
            bool pn = (nrow + 1 < N);
            if (pn) load_pair(nxt, mat, nrow, lane);
            reduce_pair(cur, q0, q1, q2, q3, row, lane, k);
            if (pn) cur = nxt;
        }
    }
    // Tail (N odd): at most one leftover single row.
    if (row < N) {
        const float4* ra = reinterpret_cast<const float4*>(mat + (size_t)row * D);
        float4 a0 = __ldcs(ra + lane +  0);
        float4 a1 = __ldcs(ra + lane + 32);
        float4 a2 = __ldcs(ra + lane + 64);
        float4 a3 = __ldcs(ra + lane + 96);
        float s = l1_4(a0, q0) + l1_4(a1, q1) + l1_4(a2, q2) + l1_4(a3, q3);
        #pragma unroll
        for (int o = 16; o > 0; o >>= 1)
            s += __shfl_xor_sync(0xFFFFFFFFu, s, o);
        if (lane == 0) insert3(mkkey(s, (unsigned)row), k);
    }

    // Merge lanes 0 and 16 (others hold KEY_MAX), then block merge.
    warp_merge3(k);

    __shared__ unsigned long long sk[WARPS1 * KSEL];
    if (lane == 0) {
        #pragma unroll
        for (int j = 0; j < KSEL; j++) sk[warp * KSEL + j] = k[j];
    }
    __syncthreads();
    if (threadIdx.x == 0) {
        unsigned long long bk[3] = {KEY_MAX, KEY_MAX, KEY_MAX};
        #pragma unroll
        for (int j = 0; j < WARPS1 * KSEL; j++) insert3(sk[j], bk);
        #pragma unroll
        for (int j = 0; j < KSEL; j++) g_cand[blockIdx.x * KSEL + j] = bk[j];
    }

    // Last-block-done global merge.
    __shared__ int s_last;
    if (threadIdx.x == 0) {
        __threadfence();
        unsigned v = atomicAdd(&g_counter, 1u);
        s_last = (v == BLOCKS1 - 1) ? 1 : 0;
    }
    __syncthreads();
    if (!s_last) return;

    unsigned long long m[3] = {KEY_MAX, KEY_MAX, KEY_MAX};
    volatile unsigned long long* cand = g_cand;
    for (int j = threadIdx.x; j < NCAND; j += THREADS1)
        insert3(cand[j], m);
    warp_merge3(m);

    __shared__ unsigned long long fk[WARPS1 * KSEL];
    if (lane == 0) {
        #pragma unroll
        for (int j = 0; j < KSEL; j++) fk[warp * KSEL + j] = m[j];
    }
    __syncthreads();
    if (threadIdx.x == 0) {
        unsigned long long bk[3] = {KEY_MAX, KEY_MAX, KEY_MAX};
        #pragma unroll
        for (int j = 0; j < WARPS1 * KSEL; j++) insert3(fk[j], bk);
        unsigned i0 = (unsigned)(bk[0] & 0xFFFFFFFFull);
        unsigned i1 = (unsigned)(bk[1] & 0xFFFFFFFFull);
        unsigned i2 = (unsigned)(bk[2] & 0xFFFFFFFFull);
        out[0] = (pseudo[i0] + pseudo[i1] + pseudo[i2]) * (1.0f / 3.0f);
        g_counter = 0;   // reset for next graph replay
    }
}

extern "C" void kernel_launch(void* const* d_in, const int* in_sizes, int n_in,
                              void* d_out, int out_size) {
    const float* query  = (const float*)d_in[0];
    const float* mat    = (const float*)d_in[1];
    const float* pseudo = (const float*)d_in[2];
    float* out = (float*)d_out;
    const int N = in_sizes[2];

    knn_fused_kernel<<<BLOCKS1, THREADS1>>>(query, mat, pseudo, out, N);
}